// round 15
// baseline (speedup 1.0000x reference)
#include <cuda_runtime.h>
#include <cuda_fp16.h>
#include <cstdint>

#define BATCH 2
#define SEQ   1024
#define HS    768
#define NH    12
#define HD    64
#define WIN   64
#define HALF  32
#define MTOK  (BATCH*SEQ)   // 2048
#define NX    (MTOK*HS)
#define NW    (HS*HS)
#define BK    64
#define NKC   (HS / BK)     // 12

// ---------------------------------------------------------------------------
// Device-global scratch
// ---------------------------------------------------------------------------
__device__ __half g_qh[NX], g_kh[NX], g_vh[NX];
__device__ __half g_xh[NX];
__device__ __half g_ch[NX];
__device__ __half g_wqh[NW], g_wkh[NW], g_wvh[NW], g_woh[NW];

// ---------------------------------------------------------------------------
// PTX helpers
// ---------------------------------------------------------------------------
__device__ __forceinline__ uint32_t smem_u32(const void* p) {
    uint32_t a;
    asm("{ .reg .u64 t; cvta.to.shared.u64 t, %1; cvt.u32.u64 %0, t; }" : "=r"(a) : "l"(p));
    return a;
}
__device__ __forceinline__ void cp16(uint32_t dst, const void* src) {
    asm volatile("cp.async.cg.shared.global [%0], [%1], 16;" :: "r"(dst), "l"(src));
}
#define CP_COMMIT() asm volatile("cp.async.commit_group;")
#define CP_WAIT0()  asm volatile("cp.async.wait_group 0;")
#define CP_WAIT1()  asm volatile("cp.async.wait_group 1;")

__device__ __forceinline__ void ldsm4(uint32_t* r, uint32_t addr) {
    asm volatile("ldmatrix.sync.aligned.m8n8.x4.shared.b16 {%0,%1,%2,%3}, [%4];"
        : "=r"(r[0]), "=r"(r[1]), "=r"(r[2]), "=r"(r[3]) : "r"(addr));
}
__device__ __forceinline__ void mma_f16(float* d, const uint32_t* a, uint32_t b0, uint32_t b1) {
    asm volatile(
        "mma.sync.aligned.m16n8k16.row.col.f32.f16.f16.f32 "
        "{%0,%1,%2,%3}, {%4,%5,%6,%7}, {%8,%9}, {%0,%1,%2,%3};"
        : "+f"(d[0]), "+f"(d[1]), "+f"(d[2]), "+f"(d[3])
        : "r"(a[0]), "r"(a[1]), "r"(a[2]), "r"(a[3]), "r"(b0), "r"(b1));
}

// ===========================================================================
// QKV GEMM (fp16, R13-proven): CTA 128x256, 8 warps (2M x 4N), warp 64x64,
// 1 CTA/SM.  BK=64, row 128B padded to 144B stride.
// Stage: A(128r)@0, B(256r)@18432 = 55296 B, 3 stages.
// ===========================================================================
#define QSTG  55296
#define SMEM_QKV (3 * QSTG)

__device__ __forceinline__ void load_q(
    uint32_t sb, int st, int kc, const __half* __restrict__ W,
    int by, int bx, int tid)
{
    const int k0 = kc * BK;
    const uint32_t base = sb + (uint32_t)st * QSTG;
    #pragma unroll
    for (int it = 0; it < 12; it++) {
        int idx = it * 256 + tid;          // 0..3071
        int r   = idx >> 3;                // 0..383
        int cb  = idx & 7;
        const __half* src; uint32_t toff; int row;
        if (r < 128) { src = g_xh + (size_t)(by * 128 + r) * HS;         toff = 0;     row = r; }
        else         { src = W    + (size_t)(bx * 256 + (r - 128)) * HS; toff = 18432; row = r - 128; }
        cp16(base + toff + (uint32_t)row * 144 + (uint32_t)cb * 16, src + k0 + cb * 8);
    }
}

__global__ __launch_bounds__(256, 1) void qkv_kernel(
    const float* __restrict__ bq, const float* __restrict__ bk, const float* __restrict__ bv)
{
    const __half* W; const float* bias; __half* C;
    if (blockIdx.z == 0)      { W = g_wqh; bias = bq; C = g_qh; }
    else if (blockIdx.z == 1) { W = g_wkh; bias = bk; C = g_kh; }
    else                      { W = g_wvh; bias = bv; C = g_vh; }

    extern __shared__ char smem[];
    const uint32_t sb = smem_u32(smem);
    const int tid  = threadIdx.x;
    const int lane = tid & 31;
    const int warp = tid >> 5;
    const int wm   = warp & 1;
    const int wn   = warp >> 1;
    const int bx = blockIdx.x, by = blockIdx.y;

    float acc[4][8][4];
    #pragma unroll
    for (int i = 0; i < 4; i++)
        #pragma unroll
        for (int j = 0; j < 8; j++)
            #pragma unroll
            for (int r = 0; r < 4; r++) acc[i][j][r] = 0.f;

    load_q(sb, 0, 0, W, by, bx, tid); CP_COMMIT();
    load_q(sb, 1, 1, W, by, bx, tid); CP_COMMIT();

    const uint32_t arow = (uint32_t)(lane & 15);
    const uint32_t asel = (uint32_t)(lane >> 4) * 16;

    for (int kc = 0; kc < NKC; kc++) {
        if (kc + 1 < NKC) { CP_WAIT1(); } else { CP_WAIT0(); }
        __syncthreads();
        if (kc + 2 < NKC) {
            load_q(sb, (kc + 2) % 3, kc + 2, W, by, bx, tid);
            CP_COMMIT();
        }
        const uint32_t base = sb + (uint32_t)(kc % 3) * QSTG;

        #pragma unroll
        for (int ks = 0; ks < 4; ks++) {
            const uint32_t colb = (uint32_t)ks * 32 + asel;
            uint32_t ah[4][4];
            #pragma unroll
            for (int i = 0; i < 4; i++) {
                uint32_t ro = (uint32_t)(wm * 64 + i * 16) + arow;
                ldsm4(ah[i], base + ro * 144 + colb);
            }
            #pragma unroll
            for (int jj = 0; jj < 4; jj++) {
                uint32_t bf[4];
                uint32_t ro = (uint32_t)(wn * 64 + jj * 16) + arow;
                ldsm4(bf, base + 18432 + ro * 144 + colb);
                #pragma unroll
                for (int i = 0; i < 4; i++) {
                    mma_f16(acc[i][jj * 2 + 0], ah[i], bf[0], bf[2]);
                    mma_f16(acc[i][jj * 2 + 1], ah[i], bf[1], bf[3]);
                }
            }
        }
        // no trailing barrier: 3-stage rotation makes the kc+2 write WAR-safe
    }

    const int g  = lane >> 2;
    const int tg = lane & 3;
    #pragma unroll
    for (int i = 0; i < 4; i++) {
        const int row = by * 128 + wm * 64 + i * 16 + g;
        #pragma unroll
        for (int jj = 0; jj < 4; jj++) {
            #pragma unroll
            for (int s = 0; s < 2; s++) {
                const int col = bx * 256 + wn * 64 + jj * 16 + s * 8 + tg * 2;
                const float* a = acc[i][jj * 2 + s];
                const float b0 = bias[col], b1 = bias[col + 1];
                *(__half2*)&C[(size_t)row * HS + col]       = __floats2half2_rn(a[0] + b0, a[1] + b1);
                *(__half2*)&C[(size_t)(row + 8) * HS + col] = __floats2half2_rn(a[2] + b0, a[3] + b1);
            }
        }
    }
}

// ===========================================================================
// Output projection (fp16): CTA 128x96, 6 warps (2M x 3N), warp 64x32.
// mma:ldsm ratio 2.67 (was 2.0); grid (8,16)=128 = one clean CTA/SM wave.
// BK=64, row stride 144B.  Stage: A(128r)@0, B(96r)@18432 = 32256 B, 3 st.
// ===========================================================================
#define OSTG  32256
#define SMEM_OUT (3 * OSTG)

__device__ __forceinline__ void load_o(
    uint32_t sb, int st, int kc, int by, int bx, int tid)
{
    const int k0 = kc * BK;
    const uint32_t base = sb + (uint32_t)st * OSTG;
    #pragma unroll
    for (int it = 0; it < 10; it++) {
        int idx = it * 192 + tid;          // 0..1919, valid < 1792
        if (idx < 1792) {
            int r  = idx >> 3;             // 0..223
            int cb = idx & 7;
            const __half* src; uint32_t toff; int row;
            if (r < 128) { src = g_ch  + (size_t)(by * 128 + r) * HS;        toff = 0;     row = r; }
            else         { src = g_woh + (size_t)(bx * 96 + (r - 128)) * HS; toff = 18432; row = r - 128; }
            cp16(base + toff + (uint32_t)row * 144 + (uint32_t)cb * 16, src + k0 + cb * 8);
        }
    }
}

__global__ __launch_bounds__(192, 1) void out_kernel(
    const float* __restrict__ bo, float* __restrict__ Cout)
{
    extern __shared__ char smem[];
    const uint32_t sb = smem_u32(smem);
    const int tid  = threadIdx.x;
    const int lane = tid & 31;
    const int warp = tid >> 5;
    const int wm   = warp & 1;          // 0..1 -> M*64
    const int wn   = warp >> 1;         // 0..2 -> N*32
    const int bx = blockIdx.x, by = blockIdx.y;

    float acc[4][4][4];
    #pragma unroll
    for (int i = 0; i < 4; i++)
        #pragma unroll
        for (int j = 0; j < 4; j++)
            #pragma unroll
            for (int r = 0; r < 4; r++) acc[i][j][r] = 0.f;

    load_o(sb, 0, 0, by, bx, tid); CP_COMMIT();
    load_o(sb, 1, 1, by, bx, tid); CP_COMMIT();

    const uint32_t arow = (uint32_t)(lane & 15);
    const uint32_t asel = (uint32_t)(lane >> 4) * 16;

    for (int kc = 0; kc < NKC; kc++) {
        if (kc + 1 < NKC) { CP_WAIT1(); } else { CP_WAIT0(); }
        __syncthreads();
        if (kc + 2 < NKC) {
            load_o(sb, (kc + 2) % 3, kc + 2, by, bx, tid);
            CP_COMMIT();
        }
        const uint32_t base = sb + (uint32_t)(kc % 3) * OSTG;

        #pragma unroll
        for (int ks = 0; ks < 4; ks++) {
            const uint32_t colb = (uint32_t)ks * 32 + asel;
            uint32_t ah[4][4];
            #pragma unroll
            for (int i = 0; i < 4; i++) {
                uint32_t ro = (uint32_t)(wm * 64 + i * 16) + arow;
                ldsm4(ah[i], base + ro * 144 + colb);
            }
            #pragma unroll
            for (int jj = 0; jj < 2; jj++) {
                uint32_t bf[4];
                uint32_t ro = (uint32_t)(wn * 32 + jj * 16) + arow;
                ldsm4(bf, base + 18432 + ro * 144 + colb);
                #pragma unroll
                for (int i = 0; i < 4; i++) {
                    mma_f16(acc[i][jj * 2 + 0], ah[i], bf[0], bf[2]);
                    mma_f16(acc[i][jj * 2 + 1], ah[i], bf[1], bf[3]);
                }
            }
        }
        // no trailing barrier (3-stage WAR-safe)
    }

    const int g  = lane >> 2;
    const int tg = lane & 3;
    #pragma unroll
    for (int i = 0; i < 4; i++) {
        const int row = by * 128 + wm * 64 + i * 16 + g;
        #pragma unroll
        for (int jj = 0; jj < 2; jj++) {
            #pragma unroll
            for (int s = 0; s < 2; s++) {
                const int col = bx * 96 + wn * 32 + jj * 16 + s * 8 + tg * 2;
                const float* a = acc[i][jj * 2 + s];
                const float b0 = bo[col], b1 = bo[col + 1];
                *(float2*)&Cout[(size_t)row * HS + col]       = make_float2(a[0] + b0, a[1] + b1);
                *(float2*)&Cout[(size_t)(row + 8) * HS + col] = make_float2(a[2] + b0, a[3] + b1);
            }
        }
    }
}

// ---------------------------------------------------------------------------
// Convert fp32 -> fp16 (X + 4 weights). 8 floats/thread/iter.
// ---------------------------------------------------------------------------
__global__ void cvt_kernel(
    const float* __restrict__ X,
    const float* __restrict__ Wq, const float* __restrict__ Wk,
    const float* __restrict__ Wv, const float* __restrict__ Wo)
{
    const int tot8 = (NX + 4 * NW) / 8;
    for (int i8 = blockIdx.x * blockDim.x + threadIdx.x; i8 < tot8; i8 += gridDim.x * blockDim.x) {
        int i = i8 * 8;
        const float* src; __half* dst; int r;
        if (i < NX) { src = X; dst = g_xh; r = i; }
        else {
            int j = i - NX; int w = j / NW; r = j - w * NW;
            if (w == 0)      { src = Wq; dst = g_wqh; }
            else if (w == 1) { src = Wk; dst = g_wkh; }
            else if (w == 2) { src = Wv; dst = g_wvh; }
            else             { src = Wo; dst = g_woh; }
        }
        float4 x0 = *(const float4*)(src + r);
        float4 x1 = *(const float4*)(src + r + 4);
        *(__half2*)(dst + r)     = __floats2half2_rn(x0.x, x0.y);
        *(__half2*)(dst + r + 2) = __floats2half2_rn(x0.z, x0.w);
        *(__half2*)(dst + r + 4) = __floats2half2_rn(x1.x, x1.y);
        *(__half2*)(dst + r + 6) = __floats2half2_rn(x1.z, x1.w);
    }
}

// ===========================================================================
// Sliding-window attention via HMMA (R13-proven version, no overlay).
// ===========================================================================
#define SMEM_ATTN 51200

__global__ __launch_bounds__(384) void attn_kernel()
{
    extern __shared__ char smc[];
    const uint32_t sb = smem_u32(smc);
    __half* Qh = (__half*)smc;              // stride 72 halfs (144B)
    __half* Kh = (__half*)(smc + 4608);     // stride 72
    __half* Vt = (__half*)(smc + 18432);    // stride 104 halfs (208B)
    float*  Ss = (float*)(smc + 31744);     // stride 100 floats (400B)
    __half* Ph = (__half*)(smc + 44544);    // stride 104

    const int s0 = blockIdx.x * 32;
    const int h  = blockIdx.y;
    const int b  = blockIdx.z;
    const int tid = threadIdx.x;
    const int base = (b * SEQ) * HS + h * HD;

    for (int i = tid; i < 256; i += 384) {
        int r = i >> 3, c = i & 7;
        *(uint4*)&Qh[r * 72 + c * 8] = *(const uint4*)&g_qh[base + (s0 + r) * HS + c * 8];
    }
    for (int i = tid; i < 768; i += 384) {
        int r = i >> 3, c = i & 7;
        int j = s0 - HALF + r;
        uint4 v = make_uint4(0u, 0u, 0u, 0u);
        if (r < 95 && j >= 0 && j < SEQ) v = *(const uint4*)&g_kh[base + j * HS + c * 8];
        *(uint4*)&Kh[r * 72 + c * 8] = v;
    }
    for (int i = tid; i < 768; i += 384) {
        int r = i >> 3, c = i & 7;
        int j = s0 - HALF + r;
        __half hv[8];
        uint4 v = make_uint4(0u, 0u, 0u, 0u);
        if (r < 95 && j >= 0 && j < SEQ) v = *(const uint4*)&g_vh[base + j * HS + c * 8];
        *(uint4*)hv = v;
        #pragma unroll
        for (int t = 0; t < 8; t++) Vt[(c * 8 + t) * 104 + r] = hv[t];
    }
    for (int i = tid; i < 1664; i += 384) ((uint32_t*)Ph)[i] = 0u;
    __syncthreads();

    const int lane = tid & 31;
    const int warp = tid >> 5;
    const uint32_t arow = (uint32_t)(lane & 15);
    const uint32_t asel = (uint32_t)(lane >> 4) * 16;
    const uint32_t qb = sb;
    const uint32_t kb = sb + 4608;
    const uint32_t vb = sb + 18432;
    const uint32_t pb = sb + 44544;

    {
        const int wm = warp & 1;
        const int wn = warp >> 1;       // 0..5
        float c0[4] = {0.f, 0.f, 0.f, 0.f};
        float c1[4] = {0.f, 0.f, 0.f, 0.f};
        #pragma unroll
        for (int ks = 0; ks < 4; ks++) {
            const uint32_t colb = (uint32_t)ks * 32 + asel;
            uint32_t a[4], bf[4];
            ldsm4(a,  qb + ((uint32_t)(wm * 16) + arow) * 144 + colb);
            ldsm4(bf, kb + ((uint32_t)(wn * 16) + arow) * 144 + colb);
            mma_f16(c0, a, bf[0], bf[2]);
            mma_f16(c1, a, bf[1], bf[3]);
        }
        const int g  = lane >> 2;
        const int tg = lane & 3;
        const int row = wm * 16 + g;
        const int col = wn * 16 + tg * 2;
        *(float2*)&Ss[row * 100 + col]           = make_float2(c0[0], c0[1]);
        *(float2*)&Ss[(row + 8) * 100 + col]     = make_float2(c0[2], c0[3]);
        *(float2*)&Ss[row * 100 + col + 8]       = make_float2(c1[0], c1[1]);
        *(float2*)&Ss[(row + 8) * 100 + col + 8] = make_float2(c1[2], c1[3]);
    }
    __syncthreads();

    for (int q = warp; q < 32; q += 12) {
        float sc0 = Ss[q * 100 + q + lane]      * 0.125f;
        float sc1 = Ss[q * 100 + q + lane + 32] * 0.125f;
        float m = fmaxf(sc0, sc1);
        #pragma unroll
        for (int o = 16; o; o >>= 1) m = fmaxf(m, __shfl_xor_sync(0xFFFFFFFFu, m, o));
        float e0 = __expf(sc0 - m);
        float e1 = __expf(sc1 - m);
        float sum = e0 + e1;
        #pragma unroll
        for (int o = 16; o; o >>= 1) sum += __shfl_xor_sync(0xFFFFFFFFu, sum, o);
        float inv = 1.f / sum;
        Ph[q * 104 + q + lane]      = __float2half(e0 * inv);
        Ph[q * 104 + q + lane + 32] = __float2half(e1 * inv);
    }
    __syncthreads();

    if (warp < 8) {
        const int wm = warp & 1;
        const int wn = warp >> 1;       // 0..3
        float c0[4] = {0.f, 0.f, 0.f, 0.f};
        float c1[4] = {0.f, 0.f, 0.f, 0.f};
        #pragma unroll
        for (int ks = 0; ks < 6; ks++) {
            const uint32_t colb = (uint32_t)ks * 32 + asel;
            uint32_t a[4], bf[4];
            ldsm4(a,  pb + ((uint32_t)(wm * 16) + arow) * 208 + colb);
            ldsm4(bf, vb + ((uint32_t)(wn * 16) + arow) * 208 + colb);
            mma_f16(c0, a, bf[0], bf[2]);
            mma_f16(c1, a, bf[1], bf[3]);
        }
        const int g  = lane >> 2;
        const int tg = lane & 3;
        const int q  = wm * 16 + g;
        const int d0 = wn * 16 + tg * 2;
        *(__half2*)&g_ch[base + (s0 + q) * HS + d0]         = __floats2half2_rn(c0[0], c0[1]);
        *(__half2*)&g_ch[base + (s0 + q + 8) * HS + d0]     = __floats2half2_rn(c0[2], c0[3]);
        *(__half2*)&g_ch[base + (s0 + q) * HS + d0 + 8]     = __floats2half2_rn(c1[0], c1[1]);
        *(__half2*)&g_ch[base + (s0 + q + 8) * HS + d0 + 8] = __floats2half2_rn(c1[2], c1[3]);
    }
}

// ---------------------------------------------------------------------------
extern "C" void kernel_launch(void* const* d_in, const int* in_sizes, int n_in,
                              void* d_out, int out_size)
{
    const float* X  = (const float*)d_in[0];
    const float* Wq = (const float*)d_in[1];
    const float* bq = (const float*)d_in[2];
    const float* Wk = (const float*)d_in[3];
    const float* bk = (const float*)d_in[4];
    const float* Wv = (const float*)d_in[5];
    const float* bv = (const float*)d_in[6];
    const float* Wo = (const float*)d_in[7];
    const float* bo = (const float*)d_in[8];
    float* out = (float*)d_out;

    static bool attr_done = false;
    if (!attr_done) {
        cudaFuncSetAttribute(qkv_kernel,  cudaFuncAttributeMaxDynamicSharedMemorySize, SMEM_QKV);
        cudaFuncSetAttribute(out_kernel,  cudaFuncAttributeMaxDynamicSharedMemorySize, SMEM_OUT);
        cudaFuncSetAttribute(attn_kernel, cudaFuncAttributeMaxDynamicSharedMemorySize, SMEM_ATTN);
        attr_done = true;
    }

    cvt_kernel<<<592, 256>>>(X, Wq, Wk, Wv, Wo);

    dim3 qkv_grid(HS / 256, MTOK / 128, 3);    // (3, 16, 3) = 144 ~ one wave
    qkv_kernel<<<qkv_grid, 256, SMEM_QKV>>>(bq, bk, bv);

    dim3 attn_grid(SEQ / 32, NH, BATCH);       // (32, 12, 2) = 768
    attn_kernel<<<attn_grid, 384, SMEM_ATTN>>>();

    dim3 out_grid(HS / 96, MTOK / 128, 1);     // (8, 16) = 128 = one CTA/SM wave
    out_kernel<<<out_grid, 192, SMEM_OUT>>>(bo, out);
}

// round 16
// speedup vs baseline: 1.0283x; 1.0283x over previous
#include <cuda_runtime.h>
#include <cuda_fp16.h>
#include <cstdint>

#define BATCH 2
#define SEQ   1024
#define HS    768
#define NH    12
#define HD    64
#define WIN   64
#define HALF  32
#define MTOK  (BATCH*SEQ)   // 2048
#define NX    (MTOK*HS)
#define NW    (HS*HS)

// ---------------------------------------------------------------------------
// Device-global scratch
// ---------------------------------------------------------------------------
__device__ __half g_qh[NX], g_kh[NX], g_vh[NX];
__device__ __half g_xh[NX];
__device__ __half g_ch[NX];
__device__ __half g_wqh[NW], g_wkh[NW], g_wvh[NW], g_woh[NW];

// ---------------------------------------------------------------------------
// PTX helpers
// ---------------------------------------------------------------------------
__device__ __forceinline__ uint32_t smem_u32(const void* p) {
    uint32_t a;
    asm("{ .reg .u64 t; cvta.to.shared.u64 t, %1; cvt.u32.u64 %0, t; }" : "=r"(a) : "l"(p));
    return a;
}
__device__ __forceinline__ void cp16(uint32_t dst, const void* src) {
    asm volatile("cp.async.cg.shared.global [%0], [%1], 16;" :: "r"(dst), "l"(src));
}
#define CP_COMMIT() asm volatile("cp.async.commit_group;")
#define CP_WAIT0()  asm volatile("cp.async.wait_group 0;")
#define CP_WAIT1()  asm volatile("cp.async.wait_group 1;")

__device__ __forceinline__ void ldsm4(uint32_t* r, uint32_t addr) {
    asm volatile("ldmatrix.sync.aligned.m8n8.x4.shared.b16 {%0,%1,%2,%3}, [%4];"
        : "=r"(r[0]), "=r"(r[1]), "=r"(r[2]), "=r"(r[3]) : "r"(addr));
}
__device__ __forceinline__ void mma_f16(float* d, const uint32_t* a, uint32_t b0, uint32_t b1) {
    asm volatile(
        "mma.sync.aligned.m16n8k16.row.col.f32.f16.f16.f32 "
        "{%0,%1,%2,%3}, {%4,%5,%6,%7}, {%8,%9}, {%0,%1,%2,%3};"
        : "+f"(d[0]), "+f"(d[1]), "+f"(d[2]), "+f"(d[3])
        : "r"(a[0]), "r"(a[1]), "r"(a[2]), "r"(a[3]), "r"(b0), "r"(b1));
}

// ===========================================================================
// QKV GEMM (fp16): CTA 128x256, 8 warps (2M x 4N), warp 64x64, 1 CTA/SM.
// BK=128: row = 256B data padded to 272B stride (r*272 mod 128 = r*16,
// 8 distinct phases -> conflict-free ldmatrix).  NKC = 6.
// 2-stage pipeline, one barrier per k-iter (stage kc+1 = stage kc-1, which
// every thread finished reading before this iter's top barrier).
// Stage: A(128r)@0, B(256r)@34816 = 104448 B, 2 stages = 204 KB.
// ===========================================================================
#define QBK   128
#define QNKC  (HS / QBK)    // 6
#define QSTG  104448
#define SMEM_QKV (2 * QSTG)

__device__ __forceinline__ void load_q(
    uint32_t sb, int st, int kc, const __half* __restrict__ W,
    int by, int bx, int tid)
{
    const int k0 = kc * QBK;
    const uint32_t base = sb + (uint32_t)st * QSTG;
    #pragma unroll
    for (int it = 0; it < 24; it++) {
        int idx = it * 256 + tid;          // 0..6143
        int r   = idx >> 4;                // 0..383
        int cb  = idx & 15;
        const __half* src; uint32_t toff; int row;
        if (r < 128) { src = g_xh + (size_t)(by * 128 + r) * HS;         toff = 0;     row = r; }
        else         { src = W    + (size_t)(bx * 256 + (r - 128)) * HS; toff = 34816; row = r - 128; }
        cp16(base + toff + (uint32_t)row * 272 + (uint32_t)cb * 16, src + k0 + cb * 8);
    }
}

__global__ __launch_bounds__(256, 1) void qkv_kernel(
    const float* __restrict__ bq, const float* __restrict__ bk, const float* __restrict__ bv)
{
    const __half* W; const float* bias; __half* C;
    if (blockIdx.z == 0)      { W = g_wqh; bias = bq; C = g_qh; }
    else if (blockIdx.z == 1) { W = g_wkh; bias = bk; C = g_kh; }
    else                      { W = g_wvh; bias = bv; C = g_vh; }

    extern __shared__ char smem[];
    const uint32_t sb = smem_u32(smem);
    const int tid  = threadIdx.x;
    const int lane = tid & 31;
    const int warp = tid >> 5;
    const int wm   = warp & 1;
    const int wn   = warp >> 1;
    const int bx = blockIdx.x, by = blockIdx.y;

    float acc[4][8][4];
    #pragma unroll
    for (int i = 0; i < 4; i++)
        #pragma unroll
        for (int j = 0; j < 8; j++)
            #pragma unroll
            for (int r = 0; r < 4; r++) acc[i][j][r] = 0.f;

    load_q(sb, 0, 0, W, by, bx, tid); CP_COMMIT();

    const uint32_t arow = (uint32_t)(lane & 15);
    const uint32_t asel = (uint32_t)(lane >> 4) * 16;

    for (int kc = 0; kc < QNKC; kc++) {
        CP_WAIT0();            // stage kc data ready (its group is the only one)
        __syncthreads();       // all threads finished reading stage kc-1 (= kc+1's slot)
        if (kc + 1 < QNKC) {
            load_q(sb, (kc + 1) & 1, kc + 1, W, by, bx, tid);
            CP_COMMIT();
        }
        const uint32_t base = sb + (uint32_t)(kc & 1) * QSTG;

        #pragma unroll
        for (int ks = 0; ks < 8; ks++) {
            const uint32_t colb = (uint32_t)ks * 32 + asel;
            uint32_t ah[4][4];
            #pragma unroll
            for (int i = 0; i < 4; i++) {
                uint32_t ro = (uint32_t)(wm * 64 + i * 16) + arow;
                ldsm4(ah[i], base + ro * 272 + colb);
            }
            #pragma unroll
            for (int jj = 0; jj < 4; jj++) {
                uint32_t bf[4];
                uint32_t ro = (uint32_t)(wn * 64 + jj * 16) + arow;
                ldsm4(bf, base + 34816 + ro * 272 + colb);
                #pragma unroll
                for (int i = 0; i < 4; i++) {
                    mma_f16(acc[i][jj * 2 + 0], ah[i], bf[0], bf[2]);
                    mma_f16(acc[i][jj * 2 + 1], ah[i], bf[1], bf[3]);
                }
            }
        }
    }

    const int g  = lane >> 2;
    const int tg = lane & 3;
    #pragma unroll
    for (int i = 0; i < 4; i++) {
        const int row = by * 128 + wm * 64 + i * 16 + g;
        #pragma unroll
        for (int jj = 0; jj < 4; jj++) {
            #pragma unroll
            for (int s = 0; s < 2; s++) {
                const int col = bx * 256 + wn * 64 + jj * 16 + s * 8 + tg * 2;
                const float* a = acc[i][jj * 2 + s];
                const float b0 = bias[col], b1 = bias[col + 1];
                *(__half2*)&C[(size_t)row * HS + col]       = __floats2half2_rn(a[0] + b0, a[1] + b1);
                *(__half2*)&C[(size_t)(row + 8) * HS + col] = __floats2half2_rn(a[2] + b0, a[3] + b1);
            }
        }
    }
}

// ===========================================================================
// Output projection (fp16, R13-proven): CTA 64x96, 6 warps (2M x 3N),
// warp 32x32, 3 CTAs/SM.  BK=64, row stride 144B.
// Stage: A(64r)@0, B(96r)@9216 = 23040 B, 3 stages.
// ===========================================================================
#define OBK   64
#define ONKC  (HS / OBK)    // 12
#define OSTG  23040
#define SMEM_OUT (3 * OSTG)

__device__ __forceinline__ void load_o(
    uint32_t sb, int st, int kc, int by, int bx, int tid)
{
    const int k0 = kc * OBK;
    const uint32_t base = sb + (uint32_t)st * OSTG;
    #pragma unroll
    for (int it = 0; it < 7; it++) {
        int idx = it * 192 + tid;
        if (idx < 1280) {
            int r  = idx >> 3;
            int cb = idx & 7;
            const __half* src; uint32_t toff; int row;
            if (r < 64) { src = g_ch  + (size_t)(by * 64 + r) * HS;        toff = 0;    row = r; }
            else        { src = g_woh + (size_t)(bx * 96 + (r - 64)) * HS; toff = 9216; row = r - 64; }
            cp16(base + toff + (uint32_t)row * 144 + (uint32_t)cb * 16, src + k0 + cb * 8);
        }
    }
}

__global__ __launch_bounds__(192, 3) void out_kernel(
    const float* __restrict__ bo, float* __restrict__ Cout)
{
    extern __shared__ char smem[];
    const uint32_t sb = smem_u32(smem);
    const int tid  = threadIdx.x;
    const int lane = tid & 31;
    const int warp = tid >> 5;
    const int wm   = warp & 1;
    const int wn   = warp >> 1;
    const int bx = blockIdx.x, by = blockIdx.y;

    float acc[2][4][4];
    #pragma unroll
    for (int i = 0; i < 2; i++)
        #pragma unroll
        for (int j = 0; j < 4; j++)
            #pragma unroll
            for (int r = 0; r < 4; r++) acc[i][j][r] = 0.f;

    load_o(sb, 0, 0, by, bx, tid); CP_COMMIT();
    load_o(sb, 1, 1, by, bx, tid); CP_COMMIT();

    const uint32_t arow = (uint32_t)(lane & 15);
    const uint32_t asel = (uint32_t)(lane >> 4) * 16;

    for (int kc = 0; kc < ONKC; kc++) {
        if (kc + 1 < ONKC) { CP_WAIT1(); } else { CP_WAIT0(); }
        __syncthreads();
        if (kc + 2 < ONKC) {
            load_o(sb, (kc + 2) % 3, kc + 2, by, bx, tid);
            CP_COMMIT();
        }
        const uint32_t base = sb + (uint32_t)(kc % 3) * OSTG;

        #pragma unroll
        for (int ks = 0; ks < 4; ks++) {
            const uint32_t colb = (uint32_t)ks * 32 + asel;
            uint32_t ah[2][4];
            #pragma unroll
            for (int i = 0; i < 2; i++) {
                uint32_t ro = (uint32_t)(wm * 32 + i * 16) + arow;
                ldsm4(ah[i], base + ro * 144 + colb);
            }
            #pragma unroll
            for (int jj = 0; jj < 2; jj++) {
                uint32_t bf[4];
                uint32_t ro = (uint32_t)(wn * 32 + jj * 16) + arow;
                ldsm4(bf, base + 9216 + ro * 144 + colb);
                #pragma unroll
                for (int i = 0; i < 2; i++) {
                    mma_f16(acc[i][jj * 2 + 0], ah[i], bf[0], bf[2]);
                    mma_f16(acc[i][jj * 2 + 1], ah[i], bf[1], bf[3]);
                }
            }
        }
    }

    const int g  = lane >> 2;
    const int tg = lane & 3;
    #pragma unroll
    for (int i = 0; i < 2; i++) {
        const int row = by * 64 + wm * 32 + i * 16 + g;
        #pragma unroll
        for (int j = 0; j < 4; j++) {
            const int col = bx * 96 + wn * 32 + (j >> 1) * 16 + (j & 1) * 8 + tg * 2;
            const float b0 = bo[col], b1 = bo[col + 1];
            *(float2*)&Cout[(size_t)row * HS + col] =
                make_float2(acc[i][j][0] + b0, acc[i][j][1] + b1);
            *(float2*)&Cout[(size_t)(row + 8) * HS + col] =
                make_float2(acc[i][j][2] + b0, acc[i][j][3] + b1);
        }
    }
}

// ---------------------------------------------------------------------------
// Convert fp32 -> fp16 (X + 4 weights). 8 floats/thread/iter.
// ---------------------------------------------------------------------------
__global__ void cvt_kernel(
    const float* __restrict__ X,
    const float* __restrict__ Wq, const float* __restrict__ Wk,
    const float* __restrict__ Wv, const float* __restrict__ Wo)
{
    const int tot8 = (NX + 4 * NW) / 8;
    for (int i8 = blockIdx.x * blockDim.x + threadIdx.x; i8 < tot8; i8 += gridDim.x * blockDim.x) {
        int i = i8 * 8;
        const float* src; __half* dst; int r;
        if (i < NX) { src = X; dst = g_xh; r = i; }
        else {
            int j = i - NX; int w = j / NW; r = j - w * NW;
            if (w == 0)      { src = Wq; dst = g_wqh; }
            else if (w == 1) { src = Wk; dst = g_wkh; }
            else if (w == 2) { src = Wv; dst = g_wvh; }
            else             { src = Wo; dst = g_woh; }
        }
        float4 x0 = *(const float4*)(src + r);
        float4 x1 = *(const float4*)(src + r + 4);
        *(__half2*)(dst + r)     = __floats2half2_rn(x0.x, x0.y);
        *(__half2*)(dst + r + 2) = __floats2half2_rn(x0.z, x0.w);
        *(__half2*)(dst + r + 4) = __floats2half2_rn(x1.x, x1.y);
        *(__half2*)(dst + r + 6) = __floats2half2_rn(x1.z, x1.w);
    }
}

// ===========================================================================
// Sliding-window attention via HMMA (R13-proven version).
// ===========================================================================
#define SMEM_ATTN 51200

__global__ __launch_bounds__(384) void attn_kernel()
{
    extern __shared__ char smc[];
    const uint32_t sb = smem_u32(smc);
    __half* Qh = (__half*)smc;              // stride 72 halfs (144B)
    __half* Kh = (__half*)(smc + 4608);     // stride 72
    __half* Vt = (__half*)(smc + 18432);    // stride 104 halfs (208B)
    float*  Ss = (float*)(smc + 31744);     // stride 100 floats (400B)
    __half* Ph = (__half*)(smc + 44544);    // stride 104

    const int s0 = blockIdx.x * 32;
    const int h  = blockIdx.y;
    const int b  = blockIdx.z;
    const int tid = threadIdx.x;
    const int base = (b * SEQ) * HS + h * HD;

    for (int i = tid; i < 256; i += 384) {
        int r = i >> 3, c = i & 7;
        *(uint4*)&Qh[r * 72 + c * 8] = *(const uint4*)&g_qh[base + (s0 + r) * HS + c * 8];
    }
    for (int i = tid; i < 768; i += 384) {
        int r = i >> 3, c = i & 7;
        int j = s0 - HALF + r;
        uint4 v = make_uint4(0u, 0u, 0u, 0u);
        if (r < 95 && j >= 0 && j < SEQ) v = *(const uint4*)&g_kh[base + j * HS + c * 8];
        *(uint4*)&Kh[r * 72 + c * 8] = v;
    }
    for (int i = tid; i < 768; i += 384) {
        int r = i >> 3, c = i & 7;
        int j = s0 - HALF + r;
        __half hv[8];
        uint4 v = make_uint4(0u, 0u, 0u, 0u);
        if (r < 95 && j >= 0 && j < SEQ) v = *(const uint4*)&g_vh[base + j * HS + c * 8];
        *(uint4*)hv = v;
        #pragma unroll
        for (int t = 0; t < 8; t++) Vt[(c * 8 + t) * 104 + r] = hv[t];
    }
    for (int i = tid; i < 1664; i += 384) ((uint32_t*)Ph)[i] = 0u;
    __syncthreads();

    const int lane = tid & 31;
    const int warp = tid >> 5;
    const uint32_t arow = (uint32_t)(lane & 15);
    const uint32_t asel = (uint32_t)(lane >> 4) * 16;
    const uint32_t qb = sb;
    const uint32_t kb = sb + 4608;
    const uint32_t vb = sb + 18432;
    const uint32_t pb = sb + 44544;

    {
        const int wm = warp & 1;
        const int wn = warp >> 1;       // 0..5
        float c0[4] = {0.f, 0.f, 0.f, 0.f};
        float c1[4] = {0.f, 0.f, 0.f, 0.f};
        #pragma unroll
        for (int ks = 0; ks < 4; ks++) {
            const uint32_t colb = (uint32_t)ks * 32 + asel;
            uint32_t a[4], bf[4];
            ldsm4(a,  qb + ((uint32_t)(wm * 16) + arow) * 144 + colb);
            ldsm4(bf, kb + ((uint32_t)(wn * 16) + arow) * 144 + colb);
            mma_f16(c0, a, bf[0], bf[2]);
            mma_f16(c1, a, bf[1], bf[3]);
        }
        const int g  = lane >> 2;
        const int tg = lane & 3;
        const int row = wm * 16 + g;
        const int col = wn * 16 + tg * 2;
        *(float2*)&Ss[row * 100 + col]           = make_float2(c0[0], c0[1]);
        *(float2*)&Ss[(row + 8) * 100 + col]     = make_float2(c0[2], c0[3]);
        *(float2*)&Ss[row * 100 + col + 8]       = make_float2(c1[0], c1[1]);
        *(float2*)&Ss[(row + 8) * 100 + col + 8] = make_float2(c1[2], c1[3]);
    }
    __syncthreads();

    for (int q = warp; q < 32; q += 12) {
        float sc0 = Ss[q * 100 + q + lane]      * 0.125f;
        float sc1 = Ss[q * 100 + q + lane + 32] * 0.125f;
        float m = fmaxf(sc0, sc1);
        #pragma unroll
        for (int o = 16; o; o >>= 1) m = fmaxf(m, __shfl_xor_sync(0xFFFFFFFFu, m, o));
        float e0 = __expf(sc0 - m);
        float e1 = __expf(sc1 - m);
        float sum = e0 + e1;
        #pragma unroll
        for (int o = 16; o; o >>= 1) sum += __shfl_xor_sync(0xFFFFFFFFu, sum, o);
        float inv = 1.f / sum;
        Ph[q * 104 + q + lane]      = __float2half(e0 * inv);
        Ph[q * 104 + q + lane + 32] = __float2half(e1 * inv);
    }
    __syncthreads();

    if (warp < 8) {
        const int wm = warp & 1;
        const int wn = warp >> 1;       // 0..3
        float c0[4] = {0.f, 0.f, 0.f, 0.f};
        float c1[4] = {0.f, 0.f, 0.f, 0.f};
        #pragma unroll
        for (int ks = 0; ks < 6; ks++) {
            const uint32_t colb = (uint32_t)ks * 32 + asel;
            uint32_t a[4], bf[4];
            ldsm4(a,  pb + ((uint32_t)(wm * 16) + arow) * 208 + colb);
            ldsm4(bf, vb + ((uint32_t)(wn * 16) + arow) * 208 + colb);
            mma_f16(c0, a, bf[0], bf[2]);
            mma_f16(c1, a, bf[1], bf[3]);
        }
        const int g  = lane >> 2;
        const int tg = lane & 3;
        const int q  = wm * 16 + g;
        const int d0 = wn * 16 + tg * 2;
        *(__half2*)&g_ch[base + (s0 + q) * HS + d0]         = __floats2half2_rn(c0[0], c0[1]);
        *(__half2*)&g_ch[base + (s0 + q + 8) * HS + d0]     = __floats2half2_rn(c0[2], c0[3]);
        *(__half2*)&g_ch[base + (s0 + q) * HS + d0 + 8]     = __floats2half2_rn(c1[0], c1[1]);
        *(__half2*)&g_ch[base + (s0 + q + 8) * HS + d0 + 8] = __floats2half2_rn(c1[2], c1[3]);
    }
}

// ---------------------------------------------------------------------------
extern "C" void kernel_launch(void* const* d_in, const int* in_sizes, int n_in,
                              void* d_out, int out_size)
{
    const float* X  = (const float*)d_in[0];
    const float* Wq = (const float*)d_in[1];
    const float* bq = (const float*)d_in[2];
    const float* Wk = (const float*)d_in[3];
    const float* bk = (const float*)d_in[4];
    const float* Wv = (const float*)d_in[5];
    const float* bv = (const float*)d_in[6];
    const float* Wo = (const float*)d_in[7];
    const float* bo = (const float*)d_in[8];
    float* out = (float*)d_out;

    static bool attr_done = false;
    if (!attr_done) {
        cudaFuncSetAttribute(qkv_kernel,  cudaFuncAttributeMaxDynamicSharedMemorySize, SMEM_QKV);
        cudaFuncSetAttribute(out_kernel,  cudaFuncAttributeMaxDynamicSharedMemorySize, SMEM_OUT);
        cudaFuncSetAttribute(attn_kernel, cudaFuncAttributeMaxDynamicSharedMemorySize, SMEM_ATTN);
        attr_done = true;
    }

    cvt_kernel<<<592, 256>>>(X, Wq, Wk, Wv, Wo);

    dim3 qkv_grid(HS / 256, MTOK / 128, 3);    // (3, 16, 3) = 144 ~ one wave
    qkv_kernel<<<qkv_grid, 256, SMEM_QKV>>>(bq, bk, bv);

    dim3 attn_grid(SEQ / 32, NH, BATCH);       // (32, 12, 2) = 768
    attn_kernel<<<attn_grid, 384, SMEM_ATTN>>>();

    dim3 out_grid(HS / 96, MTOK / 64, 1);      // (8, 32) = 256, 3 CTAs/SM
    out_kernel<<<out_grid, 192, SMEM_OUT>>>(bo, out);
}